// round 6
// baseline (speedup 1.0000x reference)
#include <cuda_runtime.h>
#include <cstdint>
#include <cstddef>

#define Bb 16
#define Tt 4096
#define Cc 64
#define Hh 128

// scratch for q, k, v projections ([B][T][H] each, ~33.5MB each)
__device__ float g_q[Bb * Tt * Hh];
__device__ float g_k[Bb * Tt * Hh];
__device__ float g_v[Bb * Tt * Hh];

// ---------------- packed f32x2 helpers (sm_100+ PTX) ----------------
__device__ __forceinline__ unsigned long long pk2(float lo, float hi) {
    unsigned long long r;
    asm("mov.b64 %0, {%1, %2};" : "=l"(r) : "f"(lo), "f"(hi));
    return r;
}
__device__ __forceinline__ void fma2(unsigned long long& d, unsigned long long a,
                                     unsigned long long b) {
    asm("fma.rn.f32x2 %0, %1, %2, %0;" : "+l"(d) : "l"(a), "l"(b));
}
__device__ __forceinline__ void mul2(unsigned long long& d, unsigned long long a) {
    asm("mul.rn.f32x2 %0, %0, %1;" : "+l"(d) : "l"(a));
}
__device__ __forceinline__ float2 upk2(unsigned long long v) {
    float2 r;
    asm("mov.b64 {%0, %1}, %2;" : "=f"(r.x), "=f"(r.y) : "l"(v));
    return r;
}

// ---------------- projection: out[b,t,h] = sum_c x[b,t,c] * W[c,h] ----------------
#define PROJ_ROWS 16
__global__ __launch_bounds__(128) void proj_kernel(
    const float* __restrict__ x, const float* __restrict__ Wk,
    const float* __restrict__ Wq, const float* __restrict__ Wv)
{
    const int which = blockIdx.y;
    const float* W = (which == 0) ? Wq : (which == 1) ? Wk : Wv;
    float* out = (which == 0) ? g_q : (which == 1) ? g_k : g_v;
    // fold softmax scale (C^-0.5 = 0.125, n_embd NOT head_size) into q
    const float oscale = (which == 0) ? 0.125f : 1.0f;

    const int h = threadIdx.x;
    float w[Cc];
#pragma unroll
    for (int c = 0; c < Cc; c++) w[c] = W[c * Hh + h];

    __shared__ float xs[PROJ_ROWS][Cc];
    const int row0 = blockIdx.x * PROJ_ROWS;
    const float4* xg = (const float4*)(x + (size_t)row0 * Cc);
#pragma unroll
    for (int i = threadIdx.x; i < PROJ_ROWS * Cc / 4; i += 128)
        ((float4*)xs)[i] = xg[i];
    __syncthreads();

#pragma unroll
    for (int r = 0; r < PROJ_ROWS; r++) {
        float acc = 0.f;
#pragma unroll
        for (int c = 0; c < Cc; c++) acc += xs[r][c] * w[c];
        out[(size_t)(row0 + r) * Hh + h] = acc * oscale;
    }
}

// ---------------- flash attention (non-causal, online softmax) ----------------
#define BM 128           // queries per block
#define BN 64            // keys per tile
#define NTH 512          // 16 warps -> 4 per SMSP for latency hiding
#define KS_STRIDE 68     // padded stride for transposed K tile [d][k];
                         // multiple of 4 so row bases stay 16B-aligned for LDS.128

__global__ __launch_bounds__(NTH, 1) void attn_kernel(float* __restrict__ out)
{
    extern __shared__ float sm[];
    float* Qs = sm;                          // BM*Hh          = 16384 floats
    float* Ks = Qs + BM * Hh;                // Hh*KS_STRIDE   =  8704 (K transposed [d][k])
    float* Vs = Ks + Hh * KS_STRIDE;         // BN*Hh          =  8192
    float* Ps = Vs + BN * Hh;                // BM*BN          =  8192

    const int tid = threadIdx.x;
    const int ty = tid >> 4;                 // 0..31 -> query group (4 queries)
    const int tx = tid & 15;                 // 0..15 -> 4 keys (score) / 8 dims (PV)
    const int b = blockIdx.y;
    const int q0 = blockIdx.x * BM;
    const int qb = ty * 4;
    const int kb = tx * 4;

    const float* qg = g_q + ((size_t)b * Tt + q0) * Hh;
    const float* kg = g_k + (size_t)b * Tt * Hh;
    const float* vg = g_v + (size_t)b * Tt * Hh;

    // load Q tile (straight float4 copy)
    for (int i = tid; i < BM * Hh / 4; i += NTH)
        ((float4*)Qs)[i] = ((const float4*)qg)[i];

    float m[4], l[4];
    unsigned long long O2[4][4];             // 4 queries x 8 dims as f32x2 pairs
#pragma unroll
    for (int i = 0; i < 4; i++) {
        m[i] = -1e30f;
        l[i] = 0.f;
#pragma unroll
        for (int j = 0; j < 4; j++) O2[i][j] = 0ull;
    }

    for (int kt = 0; kt < Tt / BN; kt++) {
        __syncthreads();  // previous iter done with Ks/Vs/Ps (also covers Q load, iter 0)

        // load K tile transposed into [d][k] (stride 68)
        const float4* kg4 = (const float4*)(kg + (size_t)kt * BN * Hh);
        for (int i = tid; i < BN * Hh / 4; i += NTH) {
            const int kk = i >> 5;           // key row 0..63
            const int d = (i & 31) * 4;      // dim 0..124
            const float4 t = kg4[i];
            Ks[(d + 0) * KS_STRIDE + kk] = t.x;
            Ks[(d + 1) * KS_STRIDE + kk] = t.y;
            Ks[(d + 2) * KS_STRIDE + kk] = t.z;
            Ks[(d + 3) * KS_STRIDE + kk] = t.w;
        }
        // load V tile (row-major copy)
        const float4* vg4 = (const float4*)(vg + (size_t)kt * BN * Hh);
        for (int i = tid; i < BN * Hh / 4; i += NTH)
            ((float4*)Vs)[i] = vg4[i];
        __syncthreads();

        // ---- scores: s[4 queries][4 keys], accumulated as f32x2 pairs ----
        unsigned long long s2[4][2];
#pragma unroll
        for (int i = 0; i < 4; i++) { s2[i][0] = 0ull; s2[i][1] = 0ull; }

#pragma unroll 4
        for (int d4 = 0; d4 < Hh / 4; d4++) {
            float4 qv[4];
#pragma unroll
            for (int i = 0; i < 4; i++)
                qv[i] = *(const float4*)&Qs[(qb + i) * Hh + d4 * 4];
#pragma unroll
            for (int dd = 0; dd < 4; dd++) {
                const float4 kv = *(const float4*)&Ks[(d4 * 4 + dd) * KS_STRIDE + kb];
                const unsigned long long k01 = pk2(kv.x, kv.y);
                const unsigned long long k23 = pk2(kv.z, kv.w);
#pragma unroll
                for (int i = 0; i < 4; i++) {
                    const float qs = (dd == 0) ? qv[i].x : (dd == 1) ? qv[i].y
                                   : (dd == 2) ? qv[i].z : qv[i].w;
                    const unsigned long long qq = pk2(qs, qs);
                    fma2(s2[i][0], qq, k01);
                    fma2(s2[i][1], qq, k23);
                }
            }
        }

        // ---- online softmax update (row stats via width-16 shfl butterflies) ----
#pragma unroll
        for (int i = 0; i < 4; i++) {
            const float2 a = upk2(s2[i][0]);
            const float2 c = upk2(s2[i][1]);
            float tm = fmaxf(fmaxf(a.x, a.y), fmaxf(c.x, c.y));
#pragma unroll
            for (int off = 8; off >= 1; off >>= 1)
                tm = fmaxf(tm, __shfl_xor_sync(0xffffffffu, tm, off, 16));
            const float mn = fmaxf(m[i], tm);
            const float corr = __expf(m[i] - mn);
            const float p0 = __expf(a.x - mn);
            const float p1 = __expf(a.y - mn);
            const float p2 = __expf(c.x - mn);
            const float p3 = __expf(c.y - mn);
            float rs = (p0 + p1) + (p2 + p3);
#pragma unroll
            for (int off = 8; off >= 1; off >>= 1)
                rs += __shfl_xor_sync(0xffffffffu, rs, off, 16);
            l[i] = l[i] * corr + rs;
            m[i] = mn;
            const unsigned long long cc = pk2(corr, corr);
#pragma unroll
            for (int j = 0; j < 4; j++) mul2(O2[i][j], cc);
            *(float4*)&Ps[(qb + i) * BN + kb] = make_float4(p0, p1, p2, p3);
        }
        __syncthreads();

        // ---- PV: O[4 queries][8 dims] += P[.][k] * V[k][.] ----
        // k4-blocked so P is read with LDS.128 instead of scalar LDS
        const int db = tx * 8;
#pragma unroll 2
        for (int k4 = 0; k4 < BN / 4; k4++) {
            float4 pk[4];
#pragma unroll
            for (int i = 0; i < 4; i++)
                pk[i] = *(const float4*)&Ps[(qb + i) * BN + k4 * 4];
#pragma unroll
            for (int kk = 0; kk < 4; kk++) {
                const int k = k4 * 4 + kk;
                const float4 v0 = *(const float4*)&Vs[k * Hh + db];
                const float4 v1 = *(const float4*)&Vs[k * Hh + db + 4];
                const unsigned long long v01 = pk2(v0.x, v0.y);
                const unsigned long long v23 = pk2(v0.z, v0.w);
                const unsigned long long v45 = pk2(v1.x, v1.y);
                const unsigned long long v67 = pk2(v1.z, v1.w);
#pragma unroll
                for (int i = 0; i < 4; i++) {
                    const float p = (kk == 0) ? pk[i].x : (kk == 1) ? pk[i].y
                                  : (kk == 2) ? pk[i].z : pk[i].w;
                    const unsigned long long pp = pk2(p, p);
                    fma2(O2[i][0], pp, v01);
                    fma2(O2[i][1], pp, v23);
                    fma2(O2[i][2], pp, v45);
                    fma2(O2[i][3], pp, v67);
                }
            }
        }
    }

    // ---- epilogue: O /= l, write out ----
#pragma unroll
    for (int i = 0; i < 4; i++) {
        const float inv = 1.f / l[i];
        const float2 o0 = upk2(O2[i][0]);
        const float2 o1 = upk2(O2[i][1]);
        const float2 o2 = upk2(O2[i][2]);
        const float2 o3 = upk2(O2[i][3]);
        const float4 r0 = make_float4(o0.x * inv, o0.y * inv, o1.x * inv, o1.y * inv);
        const float4 r1 = make_float4(o2.x * inv, o2.y * inv, o3.x * inv, o3.y * inv);
        const size_t base = ((size_t)b * Tt + q0 + qb + i) * Hh + tx * 8;
        *(float4*)(out + base) = r0;
        *(float4*)(out + base + 4) = r1;
    }
}

extern "C" void kernel_launch(void* const* d_in, const int* in_sizes, int n_in,
                              void* d_out, int out_size) {
    const float* x  = (const float*)d_in[0];
    const float* Wk = (const float*)d_in[1];
    const float* Wq = (const float*)d_in[2];
    const float* Wv = (const float*)d_in[3];
    float* out = (float*)d_out;

    dim3 pg(Bb * Tt / PROJ_ROWS, 3);
    proj_kernel<<<pg, 128>>>(x, Wk, Wq, Wv);

    const size_t smem =
        (size_t)(BM * Hh + Hh * KS_STRIDE + BN * Hh + BM * BN) * sizeof(float);
    (void)cudaFuncSetAttribute(attn_kernel,
                               cudaFuncAttributeMaxDynamicSharedMemorySize,
                               (int)smem);
    dim3 ag(Tt / BM, Bb);
    attn_kernel<<<ag, NTH, smem>>>(out);
}

// round 8
// speedup vs baseline: 2.2492x; 2.2492x over previous
#include <cuda_runtime.h>
#include <cuda_bf16.h>
#include <cstdint>
#include <cstddef>

#define Bb 16
#define Tt 4096
#define Cc 64
#define Hh 128

// bf16 hi/lo split arrays ([b][t][h] for q,k; [b][h][t] for v-transposed)
__device__ __nv_bfloat16 g_qh[Bb * Tt * Hh];
__device__ __nv_bfloat16 g_ql[Bb * Tt * Hh];
__device__ __nv_bfloat16 g_kh[Bb * Tt * Hh];
__device__ __nv_bfloat16 g_kl[Bb * Tt * Hh];
__device__ __nv_bfloat16 g_vth[Bb * Tt * Hh];
__device__ __nv_bfloat16 g_vtl[Bb * Tt * Hh];

// ---------------- warp-MMA helpers (sm_80+ PTX, compiles for plain sm_103) ----
__device__ __forceinline__ uint32_t smem_u32(const void* p) {
    uint32_t a;
    asm("{ .reg .u64 t; cvta.to.shared.u64 t, %1; cvt.u32.u64 %0, t; }" : "=r"(a) : "l"(p));
    return a;
}
__device__ __forceinline__ void ldsm_x4(uint32_t* r, uint32_t addr) {
    asm volatile("ldmatrix.sync.aligned.m8n8.x4.shared.b16 {%0,%1,%2,%3}, [%4];"
                 : "=r"(r[0]), "=r"(r[1]), "=r"(r[2]), "=r"(r[3]) : "r"(addr));
}
__device__ __forceinline__ void mma16816(float* d, const uint32_t* a, const uint32_t* b) {
    asm volatile(
        "mma.sync.aligned.m16n8k16.row.col.f32.bf16.bf16.f32 "
        "{%0,%1,%2,%3}, {%4,%5,%6,%7}, {%8,%9}, {%0,%1,%2,%3};"
        : "+f"(d[0]), "+f"(d[1]), "+f"(d[2]), "+f"(d[3])
        : "r"(a[0]), "r"(a[1]), "r"(a[2]), "r"(a[3]), "r"(b[0]), "r"(b[1]));
}
// pack two f32 into bf16x2: lo -> low half, hi -> high half
__device__ __forceinline__ uint32_t cvt2(float lo, float hi) {
    uint32_t r;
    asm("cvt.rn.bf16x2.f32 %0, %1, %2;" : "=r"(r) : "f"(hi), "f"(lo));
    return r;
}
__device__ __forceinline__ float bf16_rn(float v) {
    return __bfloat162float(__float2bfloat16(v));
}

// ---------------- projection + bf16 hi/lo split ----------------
#define PROJ_ROWS 16
__global__ __launch_bounds__(128) void proj_kernel(
    const float* __restrict__ x, const float* __restrict__ Wk,
    const float* __restrict__ Wq, const float* __restrict__ Wv)
{
    const int which = blockIdx.y;
    const float* W = (which == 0) ? Wq : (which == 1) ? Wk : Wv;
    const float oscale = (which == 0) ? 0.125f : 1.0f;  // fold C^-0.5 (n_embd!) into q

    const int h = threadIdx.x;
    float w[Cc];
#pragma unroll
    for (int c = 0; c < Cc; c++) w[c] = W[c * Hh + h];

    __shared__ float xs[PROJ_ROWS][Cc];
    const int row0 = blockIdx.x * PROJ_ROWS;
    const int b = row0 >> 12;
    const int t0 = row0 & (Tt - 1);
    const float4* xg = (const float4*)(x + (size_t)row0 * Cc);
#pragma unroll
    for (int i = threadIdx.x; i < PROJ_ROWS * Cc / 4; i += 128)
        ((float4*)xs)[i] = xg[i];
    __syncthreads();

#pragma unroll
    for (int r = 0; r < PROJ_ROWS; r++) {
        float acc = 0.f;
#pragma unroll
        for (int c = 0; c < Cc; c++) acc += xs[r][c] * w[c];
        acc *= oscale;
        __nv_bfloat16 hi = __float2bfloat16(acc);
        __nv_bfloat16 lo = __float2bfloat16(acc - __bfloat162float(hi));
        if (which == 0) {
            const size_t idx = (size_t)(row0 + r) * Hh + h;
            g_qh[idx] = hi; g_ql[idx] = lo;
        } else if (which == 1) {
            const size_t idx = (size_t)(row0 + r) * Hh + h;
            g_kh[idx] = hi; g_kl[idx] = lo;
        } else {
            const size_t idx = ((size_t)b * Hh + h) * Tt + (t0 + r);  // transposed
            g_vth[idx] = hi; g_vtl[idx] = lo;
        }
    }
}

// ---------------- HMMA flash attention ----------------
#define BM 128
#define BN 64
#define NTH 256
#define KSTRB 272      // K/Q tile row stride bytes (128 bf16 + pad, ldmatrix conflict-free)
#define VSTRB 144      // V^T tile row stride bytes (64 bf16 + pad)

#define SM_KH 0                         // 64 * 272 = 17408
#define SM_KL 17408
#define SM_VH 34816                     // 128 * 144 = 18432
#define SM_VL 53248
#define SM_TOTAL 71680                  // Q staging (128*272=69632) reuses [0, ...)

__global__ __launch_bounds__(NTH, 1) void attn_kernel(float* __restrict__ out)
{
    extern __shared__ char sm[];
    const uint32_t sbase = smem_u32(sm);
    const int tid = threadIdx.x;
    const int wid = tid >> 5;
    const int lane = tid & 31;
    const int b = blockIdx.y;
    const int q0 = blockIdx.x * BM;

    // ---- stage Q (hi then lo) through smem, ldmatrix A-frags into registers ----
    uint32_t Qh[8][4], Ql[8][4];
    {
        const uint32_t qa = sbase + (uint32_t)(wid * 16 + (lane & 15)) * KSTRB
                          + (uint32_t)(lane >> 4) * 16;
        const __nv_bfloat16* src = g_qh + ((size_t)b * Tt + q0) * Hh;
        for (int i = tid; i < 128 * 16; i += NTH) {
            const int row = i >> 4, ch = i & 15;
            *(uint4*)(sm + row * KSTRB + ch * 16) =
                *(const uint4*)(src + (size_t)row * Hh + ch * 8);
        }
        __syncthreads();
#pragma unroll
        for (int kf = 0; kf < 8; kf++) ldsm_x4(Qh[kf], qa + kf * 32);
        __syncthreads();
        src = g_ql + ((size_t)b * Tt + q0) * Hh;
        for (int i = tid; i < 128 * 16; i += NTH) {
            const int row = i >> 4, ch = i & 15;
            *(uint4*)(sm + row * KSTRB + ch * 16) =
                *(const uint4*)(src + (size_t)row * Hh + ch * 8);
        }
        __syncthreads();
#pragma unroll
        for (int kf = 0; kf < 8; kf++) ldsm_x4(Ql[kf], qa + kf * 32);
    }

    float m0 = -1e30f, m1 = -1e30f, l0 = 0.f, l1 = 0.f;
    float O[16][4];
#pragma unroll
    for (int n = 0; n < 16; n++)
#pragma unroll
        for (int c = 0; c < 4; c++) O[n][c] = 0.f;

    const uint32_t bkrow = (uint32_t)(lane & 7) * KSTRB + (uint32_t)(lane >> 3) * 16;
    const uint32_t bvrow = (uint32_t)(lane & 7) * VSTRB + (uint32_t)(lane >> 3) * 16;

    for (int kt = 0; kt < Tt / BN; kt++) {
        __syncthreads();  // previous iteration done with smem tiles

        // ---- fill K hi/lo [key][dim] and V^T hi/lo [dim][key] tiles ----
        {
            const __nv_bfloat16* kh = g_kh + ((size_t)b * Tt + kt * BN) * Hh;
            const __nv_bfloat16* kl = g_kl + ((size_t)b * Tt + kt * BN) * Hh;
            for (int i = tid; i < 64 * 16; i += NTH) {
                const int row = i >> 4, ch = i & 15;
                *(uint4*)(sm + SM_KH + row * KSTRB + ch * 16) =
                    *(const uint4*)(kh + (size_t)row * Hh + ch * 8);
                *(uint4*)(sm + SM_KL + row * KSTRB + ch * 16) =
                    *(const uint4*)(kl + (size_t)row * Hh + ch * 8);
            }
            const __nv_bfloat16* vh = g_vth + (size_t)b * Hh * Tt + kt * BN;
            const __nv_bfloat16* vl = g_vtl + (size_t)b * Hh * Tt + kt * BN;
            for (int i = tid; i < 128 * 8; i += NTH) {
                const int d = i >> 3, ch = i & 7;
                *(uint4*)(sm + SM_VH + d * VSTRB + ch * 16) =
                    *(const uint4*)(vh + (size_t)d * Tt + ch * 8);
                *(uint4*)(sm + SM_VL + d * VSTRB + ch * 16) =
                    *(const uint4*)(vl + (size_t)d * Tt + ch * 8);
            }
        }
        __syncthreads();

        // ---- S = Qh*Kh + Qh*Kl + Ql*Kh  (16 rows x 64 keys per warp) ----
        float S[8][4];
#pragma unroll
        for (int j = 0; j < 8; j++)
#pragma unroll
            for (int c = 0; c < 4; c++) S[j][c] = 0.f;

#pragma unroll
        for (int kf2 = 0; kf2 < 4; kf2++) {          // dim chunks of 32 (2 k-frags)
#pragma unroll
            for (int jp = 0; jp < 4; jp++) {         // key n-frags, 2 at a time
                const int j = 2 * jp;
                uint32_t bh0[4], bl0[4], bh1[4], bl1[4];
                const uint32_t a0 = (uint32_t)(j * 8) * KSTRB + bkrow + (uint32_t)kf2 * 64;
                const uint32_t a1 = a0 + 8 * KSTRB;
                ldsm_x4(bh0, sbase + SM_KH + a0);
                ldsm_x4(bl0, sbase + SM_KL + a0);
                ldsm_x4(bh1, sbase + SM_KH + a1);
                ldsm_x4(bl1, sbase + SM_KL + a1);
                mma16816(S[j],     Qh[2 * kf2],     bh0);
                mma16816(S[j + 1], Qh[2 * kf2],     bh1);
                mma16816(S[j],     Qh[2 * kf2],     bl0);
                mma16816(S[j + 1], Qh[2 * kf2],     bl1);
                mma16816(S[j],     Ql[2 * kf2],     bh0);
                mma16816(S[j + 1], Ql[2 * kf2],     bh1);
                mma16816(S[j],     Qh[2 * kf2 + 1], bh0 + 2);
                mma16816(S[j + 1], Qh[2 * kf2 + 1], bh1 + 2);
                mma16816(S[j],     Qh[2 * kf2 + 1], bl0 + 2);
                mma16816(S[j + 1], Qh[2 * kf2 + 1], bl1 + 2);
                mma16816(S[j],     Ql[2 * kf2 + 1], bh0 + 2);
                mma16816(S[j + 1], Ql[2 * kf2 + 1], bh1 + 2);
            }
        }

        // ---- online softmax (rows r=lane/4 and r+8; quad shfl reductions) ----
        float mx0 = -1e30f, mx1 = -1e30f;
#pragma unroll
        for (int j = 0; j < 8; j++) {
            mx0 = fmaxf(mx0, fmaxf(S[j][0], S[j][1]));
            mx1 = fmaxf(mx1, fmaxf(S[j][2], S[j][3]));
        }
        mx0 = fmaxf(mx0, __shfl_xor_sync(0xffffffffu, mx0, 1));
        mx0 = fmaxf(mx0, __shfl_xor_sync(0xffffffffu, mx0, 2));
        mx1 = fmaxf(mx1, __shfl_xor_sync(0xffffffffu, mx1, 1));
        mx1 = fmaxf(mx1, __shfl_xor_sync(0xffffffffu, mx1, 2));
        const float nm0 = fmaxf(m0, mx0), nm1 = fmaxf(m1, mx1);
        const float c0 = __expf(m0 - nm0), c1 = __expf(m1 - nm1);
        m0 = nm0; m1 = nm1;

        float s0 = 0.f, s1 = 0.f;
#pragma unroll
        for (int j = 0; j < 8; j++) {
            S[j][0] = __expf(S[j][0] - nm0);
            S[j][1] = __expf(S[j][1] - nm0);
            S[j][2] = __expf(S[j][2] - nm1);
            S[j][3] = __expf(S[j][3] - nm1);
            s0 += S[j][0] + S[j][1];
            s1 += S[j][2] + S[j][3];
        }
        s0 += __shfl_xor_sync(0xffffffffu, s0, 1);
        s0 += __shfl_xor_sync(0xffffffffu, s0, 2);
        s1 += __shfl_xor_sync(0xffffffffu, s1, 1);
        s1 += __shfl_xor_sync(0xffffffffu, s1, 2);
        l0 = l0 * c0 + s0;
        l1 = l1 * c1 + s1;
#pragma unroll
        for (int n = 0; n < 16; n++) {
            O[n][0] *= c0; O[n][1] *= c0; O[n][2] *= c1; O[n][3] *= c1;
        }

        // ---- P -> bf16 hi/lo A-fragments (C-frag pair == A-frag half) ----
        uint32_t ah[4][4], al[4][4];
#pragma unroll
        for (int kc = 0; kc < 4; kc++) {
            const int j = 2 * kc;
#pragma unroll
            for (int h2 = 0; h2 < 2; h2++) {
                const float p0 = S[j + h2][0], p1 = S[j + h2][1];
                const float p2 = S[j + h2][2], p3 = S[j + h2][3];
                const float h0 = bf16_rn(p0), h1 = bf16_rn(p1);
                const float h2f = bf16_rn(p2), h3 = bf16_rn(p3);
                ah[kc][2 * h2]     = cvt2(h0, h1);
                ah[kc][2 * h2 + 1] = cvt2(h2f, h3);
                al[kc][2 * h2]     = cvt2(p0 - h0, p1 - h1);
                al[kc][2 * h2 + 1] = cvt2(p2 - h2f, p3 - h3);
            }
        }

        // ---- O += Ph*Vh + Ph*Vl + Pl*Vh ----
#pragma unroll
        for (int kc2 = 0; kc2 < 2; kc2++) {          // key chunks of 32 (2 k-frags)
#pragma unroll
            for (int np = 0; np < 8; np++) {         // dim n-frags, 2 at a time
                const int n = 2 * np;
                uint32_t bh0[4], bl0[4], bh1[4], bl1[4];
                const uint32_t a0 = (uint32_t)(n * 8) * VSTRB + bvrow + (uint32_t)kc2 * 64;
                const uint32_t a1 = a0 + 8 * VSTRB;
                ldsm_x4(bh0, sbase + SM_VH + a0);
                ldsm_x4(bl0, sbase + SM_VL + a0);
                ldsm_x4(bh1, sbase + SM_VH + a1);
                ldsm_x4(bl1, sbase + SM_VL + a1);
                mma16816(O[n],     ah[2 * kc2],     bh0);
                mma16816(O[n + 1], ah[2 * kc2],     bh1);
                mma16816(O[n],     ah[2 * kc2],     bl0);
                mma16816(O[n + 1], ah[2 * kc2],     bl1);
                mma16816(O[n],     al[2 * kc2],     bh0);
                mma16816(O[n + 1], al[2 * kc2],     bh1);
                mma16816(O[n],     ah[2 * kc2 + 1], bh0 + 2);
                mma16816(O[n + 1], ah[2 * kc2 + 1], bh1 + 2);
                mma16816(O[n],     ah[2 * kc2 + 1], bl0 + 2);
                mma16816(O[n + 1], ah[2 * kc2 + 1], bl1 + 2);
                mma16816(O[n],     al[2 * kc2 + 1], bh0 + 2);
                mma16816(O[n + 1], al[2 * kc2 + 1], bh1 + 2);
            }
        }
    }

    // ---- epilogue: divide by l, store ----
    const float i0 = 1.f / l0, i1 = 1.f / l1;
    const int r0 = q0 + wid * 16 + (lane >> 2);
    const int col = 2 * (lane & 3);
    float* o0 = out + ((size_t)b * Tt + r0) * Hh + col;
    float* o1 = o0 + 8 * Hh;
#pragma unroll
    for (int n = 0; n < 16; n++) {
        *(float2*)(o0 + n * 8) = make_float2(O[n][0] * i0, O[n][1] * i0);
        *(float2*)(o1 + n * 8) = make_float2(O[n][2] * i1, O[n][3] * i1);
    }
}

extern "C" void kernel_launch(void* const* d_in, const int* in_sizes, int n_in,
                              void* d_out, int out_size) {
    const float* x  = (const float*)d_in[0];
    const float* Wk = (const float*)d_in[1];
    const float* Wq = (const float*)d_in[2];
    const float* Wv = (const float*)d_in[3];
    float* out = (float*)d_out;

    dim3 pg(Bb * Tt / PROJ_ROWS, 3);
    proj_kernel<<<pg, 128>>>(x, Wk, Wq, Wv);

    (void)cudaFuncSetAttribute(attn_kernel,
                               cudaFuncAttributeMaxDynamicSharedMemorySize, SM_TOTAL);
    dim3 ag(Tt / BM, Bb);
    attn_kernel<<<ag, NTH, SM_TOTAL>>>(out);
}

// round 10
// speedup vs baseline: 3.6503x; 1.6230x over previous
#include <cuda_runtime.h>
#include <cuda_bf16.h>
#include <cstdint>
#include <cstddef>

#define Bb 16
#define Tt 4096
#define Cc 64
#define Hh 128

// bf16 hi/lo split arrays ([b][t][h] for q,k; [b][h][t] for v-transposed)
__device__ __align__(16) __nv_bfloat16 g_qh[Bb * Tt * Hh];
__device__ __align__(16) __nv_bfloat16 g_ql[Bb * Tt * Hh];
__device__ __align__(16) __nv_bfloat16 g_kh[Bb * Tt * Hh];
__device__ __align__(16) __nv_bfloat16 g_kl[Bb * Tt * Hh];
__device__ __align__(16) __nv_bfloat16 g_vth[Bb * Tt * Hh];
__device__ __align__(16) __nv_bfloat16 g_vtl[Bb * Tt * Hh];

// ---------------- warp-MMA helpers (sm_80+ PTX, compiles for plain sm_103) ----
__device__ __forceinline__ uint32_t smem_u32(const void* p) {
    uint32_t a;
    asm("{ .reg .u64 t; cvta.to.shared.u64 t, %1; cvt.u32.u64 %0, t; }" : "=r"(a) : "l"(p));
    return a;
}
__device__ __forceinline__ void ldsm_x4(uint32_t* r, uint32_t addr) {
    asm volatile("ldmatrix.sync.aligned.m8n8.x4.shared.b16 {%0,%1,%2,%3}, [%4];"
                 : "=r"(r[0]), "=r"(r[1]), "=r"(r[2]), "=r"(r[3]) : "r"(addr));
}
// NOTE: deliberately NOT volatile — lets ptxas interleave independent MMA chains
__device__ __forceinline__ void mma16816(float* d, const uint32_t* a, const uint32_t* b) {
    asm("mma.sync.aligned.m16n8k16.row.col.f32.bf16.bf16.f32 "
        "{%0,%1,%2,%3}, {%4,%5,%6,%7}, {%8,%9}, {%0,%1,%2,%3};"
        : "+f"(d[0]), "+f"(d[1]), "+f"(d[2]), "+f"(d[3])
        : "r"(a[0]), "r"(a[1]), "r"(a[2]), "r"(a[3]), "r"(b[0]), "r"(b[1]));
}
__device__ __forceinline__ uint32_t cvt2(float lo, float hi) {
    uint32_t r;
    asm("cvt.rn.bf16x2.f32 %0, %1, %2;" : "=r"(r) : "f"(hi), "f"(lo));
    return r;
}
__device__ __forceinline__ float bf16_rn(float v) {
    return __bfloat162float(__float2bfloat16(v));
}
__device__ __forceinline__ void cpa16(uint32_t dst, const void* src) {
    asm volatile("cp.async.cg.shared.global [%0], [%1], 16;" :: "r"(dst), "l"(src));
}
#define CPA_COMMIT() asm volatile("cp.async.commit_group;" ::: "memory")
#define CPA_WAIT0()  asm volatile("cp.async.wait_group 0;" ::: "memory")

// ---------------- projection + bf16 hi/lo split ----------------
#define PROJ_ROWS 16
__global__ __launch_bounds__(128) void proj_kernel(
    const float* __restrict__ x, const float* __restrict__ Wk,
    const float* __restrict__ Wq, const float* __restrict__ Wv)
{
    const int which = blockIdx.y;
    const float* W = (which == 0) ? Wq : (which == 1) ? Wk : Wv;
    const float oscale = (which == 0) ? 0.125f : 1.0f;  // fold C^-0.5 (n_embd!) into q

    const int h = threadIdx.x;
    float w[Cc];
#pragma unroll
    for (int c = 0; c < Cc; c++) w[c] = W[c * Hh + h];

    __shared__ float xs[PROJ_ROWS][Cc];
    const int row0 = blockIdx.x * PROJ_ROWS;
    const int b = row0 >> 12;
    const int t0 = row0 & (Tt - 1);
    const float4* xg = (const float4*)(x + (size_t)row0 * Cc);
#pragma unroll
    for (int i = threadIdx.x; i < PROJ_ROWS * Cc / 4; i += 128)
        ((float4*)xs)[i] = xg[i];
    __syncthreads();

#pragma unroll
    for (int r = 0; r < PROJ_ROWS; r++) {
        float acc = 0.f;
#pragma unroll
        for (int c = 0; c < Cc; c++) acc += xs[r][c] * w[c];
        acc *= oscale;
        __nv_bfloat16 hi = __float2bfloat16(acc);
        __nv_bfloat16 lo = __float2bfloat16(acc - __bfloat162float(hi));
        if (which == 0) {
            const size_t idx = (size_t)(row0 + r) * Hh + h;
            g_qh[idx] = hi; g_ql[idx] = lo;
        } else if (which == 1) {
            const size_t idx = (size_t)(row0 + r) * Hh + h;
            g_kh[idx] = hi; g_kl[idx] = lo;
        } else {
            const size_t idx = ((size_t)b * Hh + h) * Tt + (t0 + r);  // transposed
            g_vth[idx] = hi; g_vtl[idx] = lo;
        }
    }
}

// ---------------- HMMA flash attention, double-buffered ----------------
#define BM 128
#define BN 64
#define NTH 256
#define KSTRB 272      // K/Q tile row stride bytes (128 bf16 + pad)
#define VSTRB 144      // V^T tile row stride bytes (64 bf16 + pad)

// smem map: resident Q hi/lo, then two K/V buffers
#define SM_QH 0                         // 128*272 = 34816
#define SM_QL 34816
#define SM_BUF0 69632
#define BUF_SZ 71680                    // KH 17408 | KL 17408 | VH 18432 | VL 18432
#define OFF_KH 0
#define OFF_KL 17408
#define OFF_VH 34816
#define OFF_VL 53248
#define SM_TOTAL (SM_BUF0 + 2 * BUF_SZ) // 212992

__global__ __launch_bounds__(NTH, 1) void attn_kernel(float* __restrict__ out)
{
    extern __shared__ char sm[];
    const uint32_t sbase = smem_u32(sm);
    const int tid = threadIdx.x;
    const int wid = tid >> 5;
    const int lane = tid & 31;
    const int b = blockIdx.y;
    const int q0 = blockIdx.x * BM;

    // ---- stage resident Q hi/lo tiles ----
    {
        const __nv_bfloat16* qh = g_qh + ((size_t)b * Tt + q0) * Hh;
        const __nv_bfloat16* ql = g_ql + ((size_t)b * Tt + q0) * Hh;
        for (int i = tid; i < 128 * 16; i += NTH) {
            const int row = i >> 4, ch = i & 15;
            *(uint4*)(sm + SM_QH + row * KSTRB + ch * 16) =
                *(const uint4*)(qh + (size_t)row * Hh + ch * 8);
            *(uint4*)(sm + SM_QL + row * KSTRB + ch * 16) =
                *(const uint4*)(ql + (size_t)row * Hh + ch * 8);
        }
    }

    const __nv_bfloat16* kh_g = g_kh + (size_t)b * Tt * Hh;
    const __nv_bfloat16* kl_g = g_kl + (size_t)b * Tt * Hh;
    const __nv_bfloat16* vh_g = g_vth + (size_t)b * Hh * Tt;
    const __nv_bfloat16* vl_g = g_vtl + (size_t)b * Hh * Tt;

    // issue async loads of tile `kt` into buffer bp
    auto issue_tile = [&](int kt, int bp) {
        const uint32_t bb = sbase + SM_BUF0 + bp * BUF_SZ;
        const __nv_bfloat16* kh = kh_g + (size_t)kt * BN * Hh;
        const __nv_bfloat16* kl = kl_g + (size_t)kt * BN * Hh;
        const __nv_bfloat16* vh = vh_g + (size_t)kt * BN;
        const __nv_bfloat16* vl = vl_g + (size_t)kt * BN;
        for (int i = tid; i < 64 * 16; i += NTH) {
            const int row = i >> 4, ch = i & 15;
            cpa16(bb + OFF_KH + row * KSTRB + ch * 16, kh + (size_t)row * Hh + ch * 8);
            cpa16(bb + OFF_KL + row * KSTRB + ch * 16, kl + (size_t)row * Hh + ch * 8);
        }
        for (int i = tid; i < 128 * 8; i += NTH) {
            const int d = i >> 3, ch = i & 7;
            cpa16(bb + OFF_VH + d * VSTRB + ch * 16, vh + (size_t)d * Tt + ch * 8);
            cpa16(bb + OFF_VL + d * VSTRB + ch * 16, vl + (size_t)d * Tt + ch * 8);
        }
    };

    issue_tile(0, 0);
    CPA_COMMIT();

    float m0 = -1e30f, m1 = -1e30f, l0 = 0.f, l1 = 0.f;
    float O[16][4];
#pragma unroll
    for (int n = 0; n < 16; n++)
#pragma unroll
        for (int c = 0; c < 4; c++) O[n][c] = 0.f;

    const uint32_t qaH = sbase + SM_QH + (uint32_t)(wid * 16 + (lane & 15)) * KSTRB
                       + (uint32_t)(lane >> 4) * 16;
    const uint32_t qaL = qaH + (SM_QL - SM_QH);
    const uint32_t bkrow = (uint32_t)(lane & 7) * KSTRB + (uint32_t)(lane >> 3) * 16;
    const uint32_t bvrow = (uint32_t)(lane & 7) * VSTRB + (uint32_t)(lane >> 3) * 16;

    for (int kt = 0; kt < Tt / BN; kt++) {
        const int bp = kt & 1;
        const uint32_t bb = sbase + SM_BUF0 + bp * BUF_SZ;

        CPA_WAIT0();
        __syncthreads();                 // tile kt ready; everyone done with buffer 1-bp
        if (kt + 1 < Tt / BN) {
            issue_tile(kt + 1, 1 - bp);  // overlap next tile's loads with compute
            CPA_COMMIT();
        }

        // ---- S = Qh*Kh + Qh*Kl + Ql*Kh  (16 rows x 64 keys per warp) ----
        float S[8][4];
#pragma unroll
        for (int j = 0; j < 8; j++)
#pragma unroll
            for (int c = 0; c < 4; c++) S[j][c] = 0.f;

#pragma unroll
        for (int kf2 = 0; kf2 < 4; kf2++) {          // dim chunks of 32 (2 k-frags)
            uint32_t qh2[2][4], ql2[2][4];
            ldsm_x4(qh2[0], qaH + (2 * kf2) * 32);
            ldsm_x4(qh2[1], qaH + (2 * kf2 + 1) * 32);
            ldsm_x4(ql2[0], qaL + (2 * kf2) * 32);
            ldsm_x4(ql2[1], qaL + (2 * kf2 + 1) * 32);
#pragma unroll
            for (int jp = 0; jp < 4; jp++) {         // key n-frags, 2 at a time
                const int j = 2 * jp;
                uint32_t bh0[4], bl0[4], bh1[4], bl1[4];
                const uint32_t a0 = (uint32_t)(j * 8) * KSTRB + bkrow + (uint32_t)kf2 * 64;
                const uint32_t a1 = a0 + 8 * KSTRB;
                ldsm_x4(bh0, bb + OFF_KH + a0);
                ldsm_x4(bl0, bb + OFF_KL + a0);
                ldsm_x4(bh1, bb + OFF_KH + a1);
                ldsm_x4(bl1, bb + OFF_KL + a1);
                mma16816(S[j],     qh2[0], bh0);
                mma16816(S[j + 1], qh2[0], bh1);
                mma16816(S[j],     qh2[0], bl0);
                mma16816(S[j + 1], qh2[0], bl1);
                mma16816(S[j],     ql2[0], bh0);
                mma16816(S[j + 1], ql2[0], bh1);
                mma16816(S[j],     qh2[1], bh0 + 2);
                mma16816(S[j + 1], qh2[1], bh1 + 2);
                mma16816(S[j],     qh2[1], bl0 + 2);
                mma16816(S[j + 1], qh2[1], bl1 + 2);
                mma16816(S[j],     ql2[1], bh0 + 2);
                mma16816(S[j + 1], ql2[1], bh1 + 2);
            }
        }

        // ---- online softmax (rows r=lane/4 and r+8; quad shfl reductions) ----
        float mx0 = -1e30f, mx1 = -1e30f;
#pragma unroll
        for (int j = 0; j < 8; j++) {
            mx0 = fmaxf(mx0, fmaxf(S[j][0], S[j][1]));
            mx1 = fmaxf(mx1, fmaxf(S[j][2], S[j][3]));
        }
        mx0 = fmaxf(mx0, __shfl_xor_sync(0xffffffffu, mx0, 1));
        mx0 = fmaxf(mx0, __shfl_xor_sync(0xffffffffu, mx0, 2));
        mx1 = fmaxf(mx1, __shfl_xor_sync(0xffffffffu, mx1, 1));
        mx1 = fmaxf(mx1, __shfl_xor_sync(0xffffffffu, mx1, 2));
        const float nm0 = fmaxf(m0, mx0), nm1 = fmaxf(m1, mx1);
        const float c0 = __expf(m0 - nm0), c1 = __expf(m1 - nm1);
        m0 = nm0; m1 = nm1;

        float s0 = 0.f, s1 = 0.f;
#pragma unroll
        for (int j = 0; j < 8; j++) {
            S[j][0] = __expf(S[j][0] - nm0);
            S[j][1] = __expf(S[j][1] - nm0);
            S[j][2] = __expf(S[j][2] - nm1);
            S[j][3] = __expf(S[j][3] - nm1);
            s0 += S[j][0] + S[j][1];
            s1 += S[j][2] + S[j][3];
        }
        s0 += __shfl_xor_sync(0xffffffffu, s0, 1);
        s0 += __shfl_xor_sync(0xffffffffu, s0, 2);
        s1 += __shfl_xor_sync(0xffffffffu, s1, 1);
        s1 += __shfl_xor_sync(0xffffffffu, s1, 2);
        l0 = l0 * c0 + s0;
        l1 = l1 * c1 + s1;
#pragma unroll
        for (int n = 0; n < 16; n++) {
            O[n][0] *= c0; O[n][1] *= c0; O[n][2] *= c1; O[n][3] *= c1;
        }

        // ---- P -> bf16 hi/lo A-fragments (C-frag pair == A-frag half) ----
        uint32_t ah[4][4], al[4][4];
#pragma unroll
        for (int kc = 0; kc < 4; kc++) {
            const int j = 2 * kc;
#pragma unroll
            for (int h2 = 0; h2 < 2; h2++) {
                const float p0 = S[j + h2][0], p1 = S[j + h2][1];
                const float p2 = S[j + h2][2], p3 = S[j + h2][3];
                const float h0 = bf16_rn(p0), h1 = bf16_rn(p1);
                const float h2f = bf16_rn(p2), h3 = bf16_rn(p3);
                ah[kc][2 * h2]     = cvt2(h0, h1);
                ah[kc][2 * h2 + 1] = cvt2(h2f, h3);
                al[kc][2 * h2]     = cvt2(p0 - h0, p1 - h1);
                al[kc][2 * h2 + 1] = cvt2(p2 - h2f, p3 - h3);
            }
        }

        // ---- O += Ph*Vh + Ph*Vl + Pl*Vh ----
#pragma unroll
        for (int kc2 = 0; kc2 < 2; kc2++) {          // key chunks of 32 (2 k-frags)
#pragma unroll
            for (int np = 0; np < 8; np++) {         // dim n-frags, 2 at a time
                const int n = 2 * np;
                uint32_t bh0[4], bl0[4], bh1[4], bl1[4];
                const uint32_t a0 = (uint32_t)(n * 8) * VSTRB + bvrow + (uint32_t)kc2 * 64;
                const uint32_t a1 = a0 + 8 * VSTRB;
                ldsm_x4(bh0, bb + OFF_VH + a0);
                ldsm_x4(bl0, bb + OFF_VL + a0);
                ldsm_x4(bh1, bb + OFF_VH + a1);
                ldsm_x4(bl1, bb + OFF_VL + a1);
                mma16816(O[n],     ah[2 * kc2],     bh0);
                mma16816(O[n + 1], ah[2 * kc2],     bh1);
                mma16816(O[n],     ah[2 * kc2],     bl0);
                mma16816(O[n + 1], ah[2 * kc2],     bl1);
                mma16816(O[n],     al[2 * kc2],     bh0);
                mma16816(O[n + 1], al[2 * kc2],     bh1);
                mma16816(O[n],     ah[2 * kc2 + 1], bh0 + 2);
                mma16816(O[n + 1], ah[2 * kc2 + 1], bh1 + 2);
                mma16816(O[n],     ah[2 * kc2 + 1], bl0 + 2);
                mma16816(O[n + 1], ah[2 * kc2 + 1], bl1 + 2);
                mma16816(O[n],     al[2 * kc2 + 1], bh0 + 2);
                mma16816(O[n + 1], al[2 * kc2 + 1], bh1 + 2);
            }
        }
    }

    // ---- epilogue: divide by l, store ----
    const float i0 = 1.f / l0, i1 = 1.f / l1;
    const int r0 = q0 + wid * 16 + (lane >> 2);
    const int col = 2 * (lane & 3);
    float* o0 = out + ((size_t)b * Tt + r0) * Hh + col;
    float* o1 = o0 + 8 * Hh;
#pragma unroll
    for (int n = 0; n < 16; n++) {
        *(float2*)(o0 + n * 8) = make_float2(O[n][0] * i0, O[n][1] * i0);
        *(float2*)(o1 + n * 8) = make_float2(O[n][2] * i1, O[n][3] * i1);
    }
}

extern "C" void kernel_launch(void* const* d_in, const int* in_sizes, int n_in,
                              void* d_out, int out_size) {
    const float* x  = (const float*)d_in[0];
    const float* Wk = (const float*)d_in[1];
    const float* Wq = (const float*)d_in[2];
    const float* Wv = (const float*)d_in[3];
    float* out = (float*)d_out;

    dim3 pg(Bb * Tt / PROJ_ROWS, 3);
    proj_kernel<<<pg, 128>>>(x, Wk, Wq, Wv);

    (void)cudaFuncSetAttribute(attn_kernel,
                               cudaFuncAttributeMaxDynamicSharedMemorySize, SM_TOTAL);
    dim3 ag(Tt / BM, Bb);
    attn_kernel<<<ag, NTH, SM_TOTAL>>>(out);
}

// round 12
// speedup vs baseline: 3.7007x; 1.0138x over previous
#include <cuda_runtime.h>
#include <cuda_bf16.h>
#include <cstdint>
#include <cstddef>

#define Bb 16
#define Tt 4096
#define Cc 64
#define Hh 128

// bf16 hi/lo split arrays ([b][t][h] for q,k; [b][h][t] for v-transposed)
__device__ __align__(16) __nv_bfloat16 g_qh[Bb * Tt * Hh];
__device__ __align__(16) __nv_bfloat16 g_ql[Bb * Tt * Hh];
__device__ __align__(16) __nv_bfloat16 g_kh[Bb * Tt * Hh];
__device__ __align__(16) __nv_bfloat16 g_kl[Bb * Tt * Hh];
__device__ __align__(16) __nv_bfloat16 g_vth[Bb * Tt * Hh];
__device__ __align__(16) __nv_bfloat16 g_vtl[Bb * Tt * Hh];

// ---------------- warp-MMA helpers (sm_80+ PTX, compiles for plain sm_103) ----
__device__ __forceinline__ uint32_t smem_u32(const void* p) {
    uint32_t a;
    asm("{ .reg .u64 t; cvta.to.shared.u64 t, %1; cvt.u32.u64 %0, t; }" : "=r"(a) : "l"(p));
    return a;
}
__device__ __forceinline__ void ldsm_x4(uint32_t* r, uint32_t addr) {
    asm volatile("ldmatrix.sync.aligned.m8n8.x4.shared.b16 {%0,%1,%2,%3}, [%4];"
                 : "=r"(r[0]), "=r"(r[1]), "=r"(r[2]), "=r"(r[3]) : "r"(addr));
}
// NOTE: deliberately NOT volatile — lets ptxas interleave independent MMA chains
__device__ __forceinline__ void mma16816(float* d, const uint32_t* a, const uint32_t* b) {
    asm("mma.sync.aligned.m16n8k16.row.col.f32.bf16.bf16.f32 "
        "{%0,%1,%2,%3}, {%4,%5,%6,%7}, {%8,%9}, {%0,%1,%2,%3};"
        : "+f"(d[0]), "+f"(d[1]), "+f"(d[2]), "+f"(d[3])
        : "r"(a[0]), "r"(a[1]), "r"(a[2]), "r"(a[3]), "r"(b[0]), "r"(b[1]));
}
__device__ __forceinline__ uint32_t cvt2(float lo, float hi) {
    uint32_t r;
    asm("cvt.rn.bf16x2.f32 %0, %1, %2;" : "=r"(r) : "f"(hi), "f"(lo));
    return r;
}
// {hi16(b), hi16(a)} -> one packed bf16x2 (truncation split, no cvt)
__device__ __forceinline__ uint32_t prmt_hi(uint32_t a, uint32_t b) {
    uint32_t r;
    asm("prmt.b32 %0, %1, %2, 0x7632;" : "=r"(r) : "r"(a), "r"(b));
    return r;
}
__device__ __forceinline__ float ex2(float x) {
    float r;
    asm("ex2.approx.f32 %0, %1;" : "=f"(r) : "f"(x));
    return r;
}
__device__ __forceinline__ void cpa16(uint32_t dst, const void* src) {
    asm volatile("cp.async.cg.shared.global [%0], [%1], 16;" :: "r"(dst), "l"(src));
}
#define CPA_COMMIT() asm volatile("cp.async.commit_group;" ::: "memory")
#define CPA_WAIT0()  asm volatile("cp.async.wait_group 0;" ::: "memory")

// ---------------- projection + bf16 hi/lo split ----------------
#define PROJ_ROWS 16
__global__ __launch_bounds__(128) void proj_kernel(
    const float* __restrict__ x, const float* __restrict__ Wk,
    const float* __restrict__ Wq, const float* __restrict__ Wv)
{
    const int which = blockIdx.y;
    const float* W = (which == 0) ? Wq : (which == 1) ? Wk : Wv;
    // fold softmax scale C^-0.5 = 0.125 (n_embd!) AND log2(e) into q:
    // softmax then runs in base-2 (ex2 only, no pre-multiply)
    const float oscale = (which == 0) ? 0.18033688011112042f : 1.0f;

    const int h = threadIdx.x;
    float w[Cc];
#pragma unroll
    for (int c = 0; c < Cc; c++) w[c] = W[c * Hh + h];

    __shared__ float xs[PROJ_ROWS][Cc];
    const int row0 = blockIdx.x * PROJ_ROWS;
    const int b = row0 >> 12;
    const int t0 = row0 & (Tt - 1);
    const float4* xg = (const float4*)(x + (size_t)row0 * Cc);
#pragma unroll
    for (int i = threadIdx.x; i < PROJ_ROWS * Cc / 4; i += 128)
        ((float4*)xs)[i] = xg[i];
    __syncthreads();

#pragma unroll
    for (int r = 0; r < PROJ_ROWS; r++) {
        float acc = 0.f;
#pragma unroll
        for (int c = 0; c < Cc; c++) acc += xs[r][c] * w[c];
        acc *= oscale;
        __nv_bfloat16 hi = __float2bfloat16(acc);
        __nv_bfloat16 lo = __float2bfloat16(acc - __bfloat162float(hi));
        if (which == 0) {
            const size_t idx = (size_t)(row0 + r) * Hh + h;
            g_qh[idx] = hi; g_ql[idx] = lo;
        } else if (which == 1) {
            const size_t idx = (size_t)(row0 + r) * Hh + h;
            g_kh[idx] = hi; g_kl[idx] = lo;
        } else {
            const size_t idx = ((size_t)b * Hh + h) * Tt + (t0 + r);  // transposed
            g_vth[idx] = hi; g_vtl[idx] = lo;
        }
    }
}

// ---------------- HMMA flash attention, double-buffered ----------------
#define BM 128
#define BN 64
#define NTH 256
#define KSTRB 272      // K/Q tile row stride bytes (128 bf16 + pad)
#define VSTRB 144      // V^T tile row stride bytes (64 bf16 + pad)

// smem map: resident Q hi/lo, then two K/V buffers
#define SM_QH 0                         // 128*272 = 34816
#define SM_QL 34816
#define SM_BUF0 69632
#define BUF_SZ 71680                    // KH 17408 | KL 17408 | VH 18432 | VL 18432
#define OFF_KH 0
#define OFF_KL 17408
#define OFF_VH 34816
#define OFF_VL 53248
#define SM_TOTAL (SM_BUF0 + 2 * BUF_SZ) // 212992

__global__ __launch_bounds__(NTH, 1) void attn_kernel(float* __restrict__ out)
{
    extern __shared__ char sm[];
    const uint32_t sbase = smem_u32(sm);
    const int tid = threadIdx.x;
    const int wid = tid >> 5;
    const int lane = tid & 31;
    const int b = blockIdx.y;
    const int q0 = blockIdx.x * BM;

    // ---- stage resident Q hi/lo tiles ----
    {
        const __nv_bfloat16* qh = g_qh + ((size_t)b * Tt + q0) * Hh;
        const __nv_bfloat16* ql = g_ql + ((size_t)b * Tt + q0) * Hh;
        for (int i = tid; i < 128 * 16; i += NTH) {
            const int row = i >> 4, ch = i & 15;
            *(uint4*)(sm + SM_QH + row * KSTRB + ch * 16) =
                *(const uint4*)(qh + (size_t)row * Hh + ch * 8);
            *(uint4*)(sm + SM_QL + row * KSTRB + ch * 16) =
                *(const uint4*)(ql + (size_t)row * Hh + ch * 8);
        }
    }

    const __nv_bfloat16* kh_g = g_kh + (size_t)b * Tt * Hh;
    const __nv_bfloat16* kl_g = g_kl + (size_t)b * Tt * Hh;
    const __nv_bfloat16* vh_g = g_vth + (size_t)b * Hh * Tt;
    const __nv_bfloat16* vl_g = g_vtl + (size_t)b * Hh * Tt;

    // issue async loads of tile `kt` into buffer bp
    auto issue_tile = [&](int kt, int bp) {
        const uint32_t bb = sbase + SM_BUF0 + bp * BUF_SZ;
        const __nv_bfloat16* kh = kh_g + (size_t)kt * BN * Hh;
        const __nv_bfloat16* kl = kl_g + (size_t)kt * BN * Hh;
        const __nv_bfloat16* vh = vh_g + (size_t)kt * BN;
        const __nv_bfloat16* vl = vl_g + (size_t)kt * BN;
        for (int i = tid; i < 64 * 16; i += NTH) {
            const int row = i >> 4, ch = i & 15;
            cpa16(bb + OFF_KH + row * KSTRB + ch * 16, kh + (size_t)row * Hh + ch * 8);
            cpa16(bb + OFF_KL + row * KSTRB + ch * 16, kl + (size_t)row * Hh + ch * 8);
        }
        for (int i = tid; i < 128 * 8; i += NTH) {
            const int d = i >> 3, ch = i & 7;
            cpa16(bb + OFF_VH + d * VSTRB + ch * 16, vh + (size_t)d * Tt + ch * 8);
            cpa16(bb + OFF_VL + d * VSTRB + ch * 16, vl + (size_t)d * Tt + ch * 8);
        }
    };

    issue_tile(0, 0);
    CPA_COMMIT();

    float m0 = -1e30f, m1 = -1e30f, l0 = 0.f, l1 = 0.f;
    float O[16][4];
#pragma unroll
    for (int n = 0; n < 16; n++)
#pragma unroll
        for (int c = 0; c < 4; c++) O[n][c] = 0.f;

    const uint32_t qaH = sbase + SM_QH + (uint32_t)(wid * 16 + (lane & 15)) * KSTRB
                       + (uint32_t)(lane >> 4) * 16;
    const uint32_t qaL = qaH + (SM_QL - SM_QH);
    const uint32_t bkrow = (uint32_t)(lane & 7) * KSTRB + (uint32_t)(lane >> 3) * 16;
    const uint32_t bvrow = (uint32_t)(lane & 7) * VSTRB + (uint32_t)(lane >> 3) * 16;

    for (int kt = 0; kt < Tt / BN; kt++) {
        const int bp = kt & 1;
        const uint32_t bb = sbase + SM_BUF0 + bp * BUF_SZ;

        CPA_WAIT0();
        __syncthreads();                 // tile kt ready; everyone done with buffer 1-bp
        if (kt + 1 < Tt / BN) {
            issue_tile(kt + 1, 1 - bp);  // overlap next tile's loads with compute
            CPA_COMMIT();
        }

        // ---- S = Qh*Kh + Qh*Kl + Ql*Kh  (16 rows x 64 keys per warp) ----
        float S[8][4];
#pragma unroll
        for (int j = 0; j < 8; j++)
#pragma unroll
            for (int c = 0; c < 4; c++) S[j][c] = 0.f;

#pragma unroll
        for (int kf2 = 0; kf2 < 4; kf2++) {          // dim chunks of 32 (2 k-frags)
            uint32_t qh2[2][4], ql2[2][4];
            ldsm_x4(qh2[0], qaH + (2 * kf2) * 32);
            ldsm_x4(qh2[1], qaH + (2 * kf2 + 1) * 32);
            ldsm_x4(ql2[0], qaL + (2 * kf2) * 32);
            ldsm_x4(ql2[1], qaL + (2 * kf2 + 1) * 32);
#pragma unroll
            for (int hb = 0; hb < 2; hb++) {         // 2 jp-groups per batch
                uint32_t bh[2][2][4], bl[2][2][4];   // [jp-in-batch][frag a0/a1]
                // batch 8 LDSMs ahead of 24 MMAs (amortize LDS latency)
#pragma unroll
                for (int t = 0; t < 2; t++) {
                    const int j = 2 * (hb * 2 + t);
                    const uint32_t a0 = (uint32_t)(j * 8) * KSTRB + bkrow + (uint32_t)kf2 * 64;
                    const uint32_t a1 = a0 + 8 * KSTRB;
                    ldsm_x4(bh[t][0], bb + OFF_KH + a0);
                    ldsm_x4(bl[t][0], bb + OFF_KL + a0);
                    ldsm_x4(bh[t][1], bb + OFF_KH + a1);
                    ldsm_x4(bl[t][1], bb + OFF_KL + a1);
                }
#pragma unroll
                for (int t = 0; t < 2; t++) {
                    const int j = 2 * (hb * 2 + t);
                    mma16816(S[j],     qh2[0], bh[t][0]);
                    mma16816(S[j + 1], qh2[0], bh[t][1]);
                    mma16816(S[j],     qh2[0], bl[t][0]);
                    mma16816(S[j + 1], qh2[0], bl[t][1]);
                    mma16816(S[j],     ql2[0], bh[t][0]);
                    mma16816(S[j + 1], ql2[0], bh[t][1]);
                    mma16816(S[j],     qh2[1], bh[t][0] + 2);
                    mma16816(S[j + 1], qh2[1], bh[t][1] + 2);
                    mma16816(S[j],     qh2[1], bl[t][0] + 2);
                    mma16816(S[j + 1], qh2[1], bl[t][1] + 2);
                    mma16816(S[j],     ql2[1], bh[t][0] + 2);
                    mma16816(S[j + 1], ql2[1], bh[t][1] + 2);
                }
            }
        }

        // ---- online softmax in base-2 (log2e folded into q) ----
        float mx0 = -1e30f, mx1 = -1e30f;
#pragma unroll
        for (int j = 0; j < 8; j++) {
            mx0 = fmaxf(mx0, fmaxf(S[j][0], S[j][1]));
            mx1 = fmaxf(mx1, fmaxf(S[j][2], S[j][3]));
        }
        mx0 = fmaxf(mx0, __shfl_xor_sync(0xffffffffu, mx0, 1));
        mx0 = fmaxf(mx0, __shfl_xor_sync(0xffffffffu, mx0, 2));
        mx1 = fmaxf(mx1, __shfl_xor_sync(0xffffffffu, mx1, 1));
        mx1 = fmaxf(mx1, __shfl_xor_sync(0xffffffffu, mx1, 2));
        const float nm0 = fmaxf(m0, mx0), nm1 = fmaxf(m1, mx1);
        const float c0 = ex2(m0 - nm0), c1 = ex2(m1 - nm1);
        m0 = nm0; m1 = nm1;

        float s0 = 0.f, s1 = 0.f;
#pragma unroll
        for (int j = 0; j < 8; j++) {
            S[j][0] = ex2(S[j][0] - nm0);
            S[j][1] = ex2(S[j][1] - nm0);
            S[j][2] = ex2(S[j][2] - nm1);
            S[j][3] = ex2(S[j][3] - nm1);
            s0 += S[j][0] + S[j][1];
            s1 += S[j][2] + S[j][3];
        }
        s0 += __shfl_xor_sync(0xffffffffu, s0, 1);
        s0 += __shfl_xor_sync(0xffffffffu, s0, 2);
        s1 += __shfl_xor_sync(0xffffffffu, s1, 1);
        s1 += __shfl_xor_sync(0xffffffffu, s1, 2);
        l0 = l0 * c0 + s0;
        l1 = l1 * c1 + s1;
#pragma unroll
        for (int n = 0; n < 16; n++) {
            O[n][0] *= c0; O[n][1] *= c0; O[n][2] *= c1; O[n][3] *= c1;
        }

        // ---- P -> bf16 hi/lo A-fragments (truncation split + PRMT pack) ----
        uint32_t ah[4][4], al[4][4];
#pragma unroll
        for (int kc = 0; kc < 4; kc++) {
            const int j = 2 * kc;
#pragma unroll
            for (int h2 = 0; h2 < 2; h2++) {
                const float p0 = S[j + h2][0], p1 = S[j + h2][1];
                const float p2 = S[j + h2][2], p3 = S[j + h2][3];
                const uint32_t u0 = __float_as_uint(p0), u1 = __float_as_uint(p1);
                const uint32_t u2 = __float_as_uint(p2), u3 = __float_as_uint(p3);
                ah[kc][2 * h2]     = prmt_hi(u0, u1);
                ah[kc][2 * h2 + 1] = prmt_hi(u2, u3);
                const float l0f = p0 - __uint_as_float(u0 & 0xFFFF0000u);
                const float l1f = p1 - __uint_as_float(u1 & 0xFFFF0000u);
                const float l2f = p2 - __uint_as_float(u2 & 0xFFFF0000u);
                const float l3f = p3 - __uint_as_float(u3 & 0xFFFF0000u);
                al[kc][2 * h2]     = cvt2(l0f, l1f);
                al[kc][2 * h2 + 1] = cvt2(l2f, l3f);
            }
        }

        // ---- O += Ph*Vh + Ph*Vl + Pl*Vh ----
#pragma unroll
        for (int kc2 = 0; kc2 < 2; kc2++) {          // key chunks of 32 (2 k-frags)
#pragma unroll
            for (int nb = 0; nb < 4; nb++) {         // batches of 2 dim n-frag-pairs
                uint32_t bh[2][2][4], bl[2][2][4];
                // batch 8 LDSMs ahead of 24 MMAs
#pragma unroll
                for (int t = 0; t < 2; t++) {
                    const int n = 2 * (nb * 2 + t);
                    const uint32_t a0 = (uint32_t)(n * 8) * VSTRB + bvrow + (uint32_t)kc2 * 64;
                    const uint32_t a1 = a0 + 8 * VSTRB;
                    ldsm_x4(bh[t][0], bb + OFF_VH + a0);
                    ldsm_x4(bl[t][0], bb + OFF_VL + a0);
                    ldsm_x4(bh[t][1], bb + OFF_VH + a1);
                    ldsm_x4(bl[t][1], bb + OFF_VL + a1);
                }
#pragma unroll
                for (int t = 0; t < 2; t++) {
                    const int n = 2 * (nb * 2 + t);
                    mma16816(O[n],     ah[2 * kc2],     bh[t][0]);
                    mma16816(O[n + 1], ah[2 * kc2],     bh[t][1]);
                    mma16816(O[n],     ah[2 * kc2],     bl[t][0]);
                    mma16816(O[n + 1], ah[2 * kc2],     bl[t][1]);
                    mma16816(O[n],     al[2 * kc2],     bh[t][0]);
                    mma16816(O[n + 1], al[2 * kc2],     bh[t][1]);
                    mma16816(O[n],     ah[2 * kc2 + 1], bh[t][0] + 2);
                    mma16816(O[n + 1], ah[2 * kc2 + 1], bh[t][1] + 2);
                    mma16816(O[n],     ah[2 * kc2 + 1], bl[t][0] + 2);
                    mma16816(O[n + 1], ah[2 * kc2 + 1], bl[t][1] + 2);
                    mma16816(O[n],     al[2 * kc2 + 1], bh[t][0] + 2);
                    mma16816(O[n + 1], al[2 * kc2 + 1], bh[t][1] + 2);
                }
            }
        }
    }

    // ---- epilogue: divide by l, store ----
    const float i0 = 1.f / l0, i1 = 1.f / l1;
    const int r0 = q0 + wid * 16 + (lane >> 2);
    const int col = 2 * (lane & 3);
    float* o0 = out + ((size_t)b * Tt + r0) * Hh + col;
    float* o1 = o0 + 8 * Hh;
#pragma unroll
    for (int n = 0; n < 16; n++) {
        *(float2*)(o0 + n * 8) = make_float2(O[n][0] * i0, O[n][1] * i0);
        *(float2*)(o1 + n * 8) = make_float2(O[n][2] * i1, O[n][3] * i1);
    }
}

extern "C" void kernel_launch(void* const* d_in, const int* in_sizes, int n_in,
                              void* d_out, int out_size) {
    const float* x  = (const float*)d_in[0];
    const float* Wk = (const float*)d_in[1];
    const float* Wq = (const float*)d_in[2];
    const float* Wv = (const float*)d_in[3];
    float* out = (float*)d_out;

    dim3 pg(Bb * Tt / PROJ_ROWS, 3);
    proj_kernel<<<pg, 128>>>(x, Wk, Wq, Wv);

    (void)cudaFuncSetAttribute(attn_kernel,
                               cudaFuncAttributeMaxDynamicSharedMemorySize, SM_TOTAL);
    dim3 ag(Tt / BM, Bb);
    attn_kernel<<<ag, NTH, SM_TOTAL>>>(out);
}

// round 16
// speedup vs baseline: 3.9021x; 1.0544x over previous
#include <cuda_runtime.h>
#include <cuda_bf16.h>
#include <cstdint>
#include <cstddef>

#define Bb 16
#define Tt 4096
#define Cc 64
#define Hh 128

// bf16 hi/lo split arrays ([b][t][h] for q,k; [b][h][t] for v-transposed)
__device__ __align__(16) __nv_bfloat16 g_qh[Bb * Tt * Hh];
__device__ __align__(16) __nv_bfloat16 g_ql[Bb * Tt * Hh];
__device__ __align__(16) __nv_bfloat16 g_kh[Bb * Tt * Hh];
__device__ __align__(16) __nv_bfloat16 g_kl[Bb * Tt * Hh];
__device__ __align__(16) __nv_bfloat16 g_vth[Bb * Tt * Hh];
__device__ __align__(16) __nv_bfloat16 g_vtl[Bb * Tt * Hh];

// ---------------- warp-MMA helpers (sm_80+ PTX, compiles for plain sm_103) ----
__device__ __forceinline__ uint32_t smem_u32(const void* p) {
    uint32_t a;
    asm("{ .reg .u64 t; cvta.to.shared.u64 t, %1; cvt.u32.u64 %0, t; }" : "=r"(a) : "l"(p));
    return a;
}
__device__ __forceinline__ void ldsm_x4(uint32_t* r, uint32_t addr) {
    asm volatile("ldmatrix.sync.aligned.m8n8.x4.shared.b16 {%0,%1,%2,%3}, [%4];"
                 : "=r"(r[0]), "=r"(r[1]), "=r"(r[2]), "=r"(r[3]) : "r"(addr));
}
// NOTE: deliberately NOT volatile — lets ptxas interleave independent MMA chains
__device__ __forceinline__ void mma16816(float* d, const uint32_t* a, const uint32_t* b) {
    asm("mma.sync.aligned.m16n8k16.row.col.f32.bf16.bf16.f32 "
        "{%0,%1,%2,%3}, {%4,%5,%6,%7}, {%8,%9}, {%0,%1,%2,%3};"
        : "+f"(d[0]), "+f"(d[1]), "+f"(d[2]), "+f"(d[3])
        : "r"(a[0]), "r"(a[1]), "r"(a[2]), "r"(a[3]), "r"(b[0]), "r"(b[1]));
}
__device__ __forceinline__ uint32_t cvt2(float lo, float hi) {
    uint32_t r;
    asm("cvt.rn.bf16x2.f32 %0, %1, %2;" : "=r"(r) : "f"(hi), "f"(lo));
    return r;
}
// {hi16(b), hi16(a)} -> one packed bf16x2 (truncation split, no cvt)
__device__ __forceinline__ uint32_t prmt_hi(uint32_t a, uint32_t b) {
    uint32_t r;
    asm("prmt.b32 %0, %1, %2, 0x7632;" : "=r"(r) : "r"(a), "r"(b));
    return r;
}
__device__ __forceinline__ float ex2(float x) {
    float r;
    asm("ex2.approx.f32 %0, %1;" : "=f"(r) : "f"(x));
    return r;
}
__device__ __forceinline__ void cpa16(uint32_t dst, const void* src) {
    asm volatile("cp.async.cg.shared.global [%0], [%1], 16;" :: "r"(dst), "l"(src));
}
#define CPA_COMMIT() asm volatile("cp.async.commit_group;" ::: "memory")
#define CPA_WAIT0()  asm volatile("cp.async.wait_group 0;" ::: "memory")

// ---------------- projection + bf16 hi/lo split ----------------
#define PROJ_ROWS 16
__global__ __launch_bounds__(128) void proj_kernel(
    const float* __restrict__ x, const float* __restrict__ Wk,
    const float* __restrict__ Wq, const float* __restrict__ Wv)
{
    const int which = blockIdx.y;
    const float* W = (which == 0) ? Wq : (which == 1) ? Wk : Wv;
    // fold softmax scale C^-0.5 = 0.125 (n_embd!) AND log2(e) into q:
    // softmax then runs in base-2 (ex2 only, no pre-multiply)
    const float oscale = (which == 0) ? 0.18033688011112042f : 1.0f;

    const int h = threadIdx.x;
    float w[Cc];
#pragma unroll
    for (int c = 0; c < Cc; c++) w[c] = W[c * Hh + h];

    __shared__ float xs[PROJ_ROWS][Cc];
    const int row0 = blockIdx.x * PROJ_ROWS;
    const int b = row0 >> 12;
    const int t0 = row0 & (Tt - 1);
    const float4* xg = (const float4*)(x + (size_t)row0 * Cc);
#pragma unroll
    for (int i = threadIdx.x; i < PROJ_ROWS * Cc / 4; i += 128)
        ((float4*)xs)[i] = xg[i];
    __syncthreads();

#pragma unroll
    for (int r = 0; r < PROJ_ROWS; r++) {
        float acc = 0.f;
#pragma unroll
        for (int c = 0; c < Cc; c++) acc += xs[r][c] * w[c];
        acc *= oscale;
        __nv_bfloat16 hi = __float2bfloat16(acc);
        __nv_bfloat16 lo = __float2bfloat16(acc - __bfloat162float(hi));
        if (which == 0) {
            const size_t idx = (size_t)(row0 + r) * Hh + h;
            g_qh[idx] = hi; g_ql[idx] = lo;
        } else if (which == 1) {
            const size_t idx = (size_t)(row0 + r) * Hh + h;
            g_kh[idx] = hi; g_kl[idx] = lo;
        } else {
            const size_t idx = ((size_t)b * Hh + h) * Tt + (t0 + r);  // transposed
            g_vth[idx] = hi; g_vtl[idx] = lo;
        }
    }
}

// ---------------- HMMA flash attention, 2 CTAs/SM, single-buffered K/V ----------
#define BM 64
#define BN 64
#define NTH 128
#define KSTRB 272      // K/Q tile row stride bytes (128 bf16 + pad)
#define VSTRB 144      // V^T tile row stride bytes (64 bf16 + pad)

// smem map (104 KB -> two CTAs co-resident per SM):
#define SM_QH 0                         // 64*272  = 17408
#define SM_QL 17408
#define SM_KH 34816                     // 64*272  = 17408
#define SM_KL 52224
#define SM_VH 69632                     // 128*144 = 18432
#define SM_VL 88064
#define SM_TOTAL 106496

__global__ __launch_bounds__(NTH, 2) void attn_kernel(float* __restrict__ out)
{
    extern __shared__ char sm[];
    const uint32_t sbase = smem_u32(sm);
    const int tid = threadIdx.x;
    const int wid = tid >> 5;
    const int lane = tid & 31;
    const int b = blockIdx.y;
    const int q0 = blockIdx.x * BM;

    const __nv_bfloat16* kh_g = g_kh + (size_t)b * Tt * Hh;
    const __nv_bfloat16* kl_g = g_kl + (size_t)b * Tt * Hh;
    const __nv_bfloat16* vh_g = g_vth + (size_t)b * Hh * Tt;
    const __nv_bfloat16* vl_g = g_vtl + (size_t)b * Hh * Tt;

    auto issue_K = [&](int kt) {
        const __nv_bfloat16* kh = kh_g + (size_t)kt * BN * Hh;
        const __nv_bfloat16* kl = kl_g + (size_t)kt * BN * Hh;
        for (int i = tid; i < 64 * 16; i += NTH) {
            const int row = i >> 4, ch = i & 15;
            cpa16(sbase + SM_KH + row * KSTRB + ch * 16, kh + (size_t)row * Hh + ch * 8);
            cpa16(sbase + SM_KL + row * KSTRB + ch * 16, kl + (size_t)row * Hh + ch * 8);
        }
    };
    auto issue_V = [&](int kt) {
        const __nv_bfloat16* vh = vh_g + (size_t)kt * BN;
        const __nv_bfloat16* vl = vl_g + (size_t)kt * BN;
        for (int i = tid; i < 128 * 8; i += NTH) {
            const int d = i >> 3, ch = i & 7;
            cpa16(sbase + SM_VH + d * VSTRB + ch * 16, vh + (size_t)d * Tt + ch * 8);
            cpa16(sbase + SM_VL + d * VSTRB + ch * 16, vl + (size_t)d * Tt + ch * 8);
        }
    };

    // prefetch tile 0, then stage resident Q hi/lo (separate smem region)
    issue_K(0);
    issue_V(0);
    CPA_COMMIT();
    {
        const __nv_bfloat16* qh = g_qh + ((size_t)b * Tt + q0) * Hh;
        const __nv_bfloat16* ql = g_ql + ((size_t)b * Tt + q0) * Hh;
        for (int i = tid; i < 64 * 16; i += NTH) {
            const int row = i >> 4, ch = i & 15;
            *(uint4*)(sm + SM_QH + row * KSTRB + ch * 16) =
                *(const uint4*)(qh + (size_t)row * Hh + ch * 8);
            *(uint4*)(sm + SM_QL + row * KSTRB + ch * 16) =
                *(const uint4*)(ql + (size_t)row * Hh + ch * 8);
        }
    }

    float m0 = -1e30f, m1 = -1e30f, l0 = 0.f, l1 = 0.f;
    float O[16][4];
#pragma unroll
    for (int n = 0; n < 16; n++)
#pragma unroll
        for (int c = 0; c < 4; c++) O[n][c] = 0.f;

    const uint32_t qaH = sbase + SM_QH + (uint32_t)(wid * 16 + (lane & 15)) * KSTRB
                       + (uint32_t)(lane >> 4) * 16;
    const uint32_t qaL = qaH + (SM_QL - SM_QH);
    const uint32_t bkrow = (uint32_t)(lane & 7) * KSTRB + (uint32_t)(lane >> 3) * 16;
    const uint32_t bvrow = (uint32_t)(lane & 7) * VSTRB + (uint32_t)(lane >> 3) * 16;

    for (int kt = 0; kt < Tt / BN; kt++) {
        CPA_WAIT0();
        __syncthreads();                 // K(kt), V(kt) in smem; Q staged (kt=0)

        // ---- S = Qh*Kh + Qh*Kl + Ql*Kh  (16 rows x 64 keys per warp) ----
        float S[8][4];
#pragma unroll
        for (int j = 0; j < 8; j++)
#pragma unroll
            for (int c = 0; c < 4; c++) S[j][c] = 0.f;

#pragma unroll
        for (int kf2 = 0; kf2 < 4; kf2++) {          // dim chunks of 32 (2 k-frags)
            uint32_t qh2[2][4], ql2[2][4];
            ldsm_x4(qh2[0], qaH + (2 * kf2) * 32);
            ldsm_x4(qh2[1], qaH + (2 * kf2 + 1) * 32);
            ldsm_x4(ql2[0], qaL + (2 * kf2) * 32);
            ldsm_x4(ql2[1], qaL + (2 * kf2 + 1) * 32);
#pragma unroll
            for (int hb = 0; hb < 2; hb++) {         // 2 jp-groups per batch
                uint32_t bh[2][2][4], bl[2][2][4];
#pragma unroll
                for (int t = 0; t < 2; t++) {        // batch 8 LDSMs ahead of 24 MMAs
                    const int j = 2 * (hb * 2 + t);
                    const uint32_t a0 = (uint32_t)(j * 8) * KSTRB + bkrow + (uint32_t)kf2 * 64;
                    const uint32_t a1 = a0 + 8 * KSTRB;
                    ldsm_x4(bh[t][0], sbase + SM_KH + a0);
                    ldsm_x4(bl[t][0], sbase + SM_KL + a0);
                    ldsm_x4(bh[t][1], sbase + SM_KH + a1);
                    ldsm_x4(bl[t][1], sbase + SM_KL + a1);
                }
#pragma unroll
                for (int t = 0; t < 2; t++) {
                    const int j = 2 * (hb * 2 + t);
                    mma16816(S[j],     qh2[0], bh[t][0]);
                    mma16816(S[j + 1], qh2[0], bh[t][1]);
                    mma16816(S[j],     qh2[0], bl[t][0]);
                    mma16816(S[j + 1], qh2[0], bl[t][1]);
                    mma16816(S[j],     ql2[0], bh[t][0]);
                    mma16816(S[j + 1], ql2[0], bh[t][1]);
                    mma16816(S[j],     qh2[1], bh[t][0] + 2);
                    mma16816(S[j + 1], qh2[1], bh[t][1] + 2);
                    mma16816(S[j],     qh2[1], bl[t][0] + 2);
                    mma16816(S[j + 1], qh2[1], bl[t][1] + 2);
                    mma16816(S[j],     ql2[1], bh[t][0] + 2);
                    mma16816(S[j + 1], ql2[1], bh[t][1] + 2);
                }
            }
        }

        __syncthreads();                 // all warps done reading K(kt)
        if (kt + 1 < Tt / BN) {
            issue_K(kt + 1);             // K prefetch hides under softmax + PV
            CPA_COMMIT();
        }

        // ---- online softmax in base-2 (log2e folded into q) ----
        float mx0 = -1e30f, mx1 = -1e30f;
#pragma unroll
        for (int j = 0; j < 8; j++) {
            mx0 = fmaxf(mx0, fmaxf(S[j][0], S[j][1]));
            mx1 = fmaxf(mx1, fmaxf(S[j][2], S[j][3]));
        }
        mx0 = fmaxf(mx0, __shfl_xor_sync(0xffffffffu, mx0, 1));
        mx0 = fmaxf(mx0, __shfl_xor_sync(0xffffffffu, mx0, 2));
        mx1 = fmaxf(mx1, __shfl_xor_sync(0xffffffffu, mx1, 1));
        mx1 = fmaxf(mx1, __shfl_xor_sync(0xffffffffu, mx1, 2));
        const float nm0 = fmaxf(m0, mx0), nm1 = fmaxf(m1, mx1);
        const float c0 = ex2(m0 - nm0), c1 = ex2(m1 - nm1);
        m0 = nm0; m1 = nm1;

        float s0 = 0.f, s1 = 0.f;
#pragma unroll
        for (int j = 0; j < 8; j++) {
            S[j][0] = ex2(S[j][0] - nm0);
            S[j][1] = ex2(S[j][1] - nm0);
            S[j][2] = ex2(S[j][2] - nm1);
            S[j][3] = ex2(S[j][3] - nm1);
            s0 += S[j][0] + S[j][1];
            s1 += S[j][2] + S[j][3];
        }
        s0 += __shfl_xor_sync(0xffffffffu, s0, 1);
        s0 += __shfl_xor_sync(0xffffffffu, s0, 2);
        s1 += __shfl_xor_sync(0xffffffffu, s1, 1);
        s1 += __shfl_xor_sync(0xffffffffu, s1, 2);
        l0 = l0 * c0 + s0;
        l1 = l1 * c1 + s1;
#pragma unroll
        for (int n = 0; n < 16; n++) {
            O[n][0] *= c0; O[n][1] *= c0; O[n][2] *= c1; O[n][3] *= c1;
        }

        // ---- P -> bf16 hi/lo A-fragments (truncation split + PRMT pack) ----
        uint32_t ah[4][4], al[4][4];
#pragma unroll
        for (int kc = 0; kc < 4; kc++) {
            const int j = 2 * kc;
#pragma unroll
            for (int h2 = 0; h2 < 2; h2++) {
                const float p0 = S[j + h2][0], p1 = S[j + h2][1];
                const float p2 = S[j + h2][2], p3 = S[j + h2][3];
                const uint32_t u0 = __float_as_uint(p0), u1 = __float_as_uint(p1);
                const uint32_t u2 = __float_as_uint(p2), u3 = __float_as_uint(p3);
                ah[kc][2 * h2]     = prmt_hi(u0, u1);
                ah[kc][2 * h2 + 1] = prmt_hi(u2, u3);
                const float l0f = p0 - __uint_as_float(u0 & 0xFFFF0000u);
                const float l1f = p1 - __uint_as_float(u1 & 0xFFFF0000u);
                const float l2f = p2 - __uint_as_float(u2 & 0xFFFF0000u);
                const float l3f = p3 - __uint_as_float(u3 & 0xFFFF0000u);
                al[kc][2 * h2]     = cvt2(l0f, l1f);
                al[kc][2 * h2 + 1] = cvt2(l2f, l3f);
            }
        }

        // ---- O += Ph*Vh + Ph*Vl + Pl*Vh ----
#pragma unroll
        for (int kc2 = 0; kc2 < 2; kc2++) {          // key chunks of 32 (2 k-frags)
#pragma unroll
            for (int nb = 0; nb < 4; nb++) {         // batches of 2 dim n-frag-pairs
                uint32_t bh[2][2][4], bl[2][2][4];
#pragma unroll
                for (int t = 0; t < 2; t++) {        // batch 8 LDSMs ahead of 24 MMAs
                    const int n = 2 * (nb * 2 + t);
                    const uint32_t a0 = (uint32_t)(n * 8) * VSTRB + bvrow + (uint32_t)kc2 * 64;
                    const uint32_t a1 = a0 + 8 * VSTRB;
                    ldsm_x4(bh[t][0], sbase + SM_VH + a0);
                    ldsm_x4(bl[t][0], sbase + SM_VL + a0);
                    ldsm_x4(bh[t][1], sbase + SM_VH + a1);
                    ldsm_x4(bl[t][1], sbase + SM_VL + a1);
                }
#pragma unroll
                for (int t = 0; t < 2; t++) {
                    const int n = 2 * (nb * 2 + t);
                    mma16816(O[n],     ah[2 * kc2],     bh[t][0]);
                    mma16816(O[n + 1], ah[2 * kc2],     bh[t][1]);
                    mma16816(O[n],     ah[2 * kc2],     bl[t][0]);
                    mma16816(O[n + 1], ah[2 * kc2],     bl[t][1]);
                    mma16816(O[n],     al[2 * kc2],     bh[t][0]);
                    mma16816(O[n + 1], al[2 * kc2],     bh[t][1]);
                    mma16816(O[n],     ah[2 * kc2 + 1], bh[t][0] + 2);
                    mma16816(O[n + 1], ah[2 * kc2 + 1], bh[t][1] + 2);
                    mma16816(O[n],     ah[2 * kc2 + 1], bl[t][0] + 2);
                    mma16816(O[n + 1], ah[2 * kc2 + 1], bl[t][1] + 2);
                    mma16816(O[n],     al[2 * kc2 + 1], bh[t][0] + 2);
                    mma16816(O[n + 1], al[2 * kc2 + 1], bh[t][1] + 2);
                }
            }
        }

        __syncthreads();                 // all warps done reading V(kt)
        if (kt + 1 < Tt / BN) {
            issue_V(kt + 1);             // exposed only across tile boundary
            CPA_COMMIT();
        }
    }

    // ---- epilogue: divide by l, store ----
    const float i0 = 1.f / l0, i1 = 1.f / l1;
    const int r0 = q0 + wid * 16 + (lane >> 2);
    const int col = 2 * (lane & 3);
    float* o0 = out + ((size_t)b * Tt + r0) * Hh + col;
    float* o1 = o0 + 8 * Hh;
#pragma unroll
    for (int n = 0; n < 16; n++) {
        *(float2*)(o0 + n * 8) = make_float2(O[n][0] * i0, O[n][1] * i0);
        *(float2*)(o1 + n * 8) = make_float2(O[n][2] * i1, O[n][3] * i1);
    }
}

extern "C" void kernel_launch(void* const* d_in, const int* in_sizes, int n_in,
                              void* d_out, int out_size) {
    const float* x  = (const float*)d_in[0];
    const float* Wk = (const float*)d_in[1];
    const float* Wq = (const float*)d_in[2];
    const float* Wv = (const float*)d_in[3];
    float* out = (float*)d_out;

    dim3 pg(Bb * Tt / PROJ_ROWS, 3);
    proj_kernel<<<pg, 128>>>(x, Wk, Wq, Wv);

    (void)cudaFuncSetAttribute(attn_kernel,
                               cudaFuncAttributeMaxDynamicSharedMemorySize, SM_TOTAL);
    dim3 ag(Tt / BM, Bb);
    attn_kernel<<<ag, NTH, SM_TOTAL>>>(out);
}